// round 4
// baseline (speedup 1.0000x reference)
#include <cuda_runtime.h>
#include <math.h>

// Problem constants (fixed by setup_inputs)
#define B_  32
#define K_  16
#define T_  30
#define N_  128
#define n_  20
#define NN  (N_ * n_)        // 2560 nodes per batch

#define YAW_THRESH  1.0471975511965976f   // pi/3
#define INF_F       __int_as_float(0x7f800000)

__device__ __forceinline__ float fast_sqrt(float x) {
    float r;
    asm("sqrt.approx.f32 %0, %1;" : "=f"(r) : "f"(x));
    return r;
}

// Scan all nodes of batch b for timestep point (pt, v). Early-exits with 0 as
// soon as any lane in the warp finds an exact-zero-cost node:
//     unmasked  AND  d2 <= 4  AND  dot(u,v) >= 0  AND  cross^2 <= 3*dot^2
// (tan(pi/3)^2 == 3; |wrap(yaw_n - yaw_p)| == angle(u, v) because the
//  yaw = -atan2(dx, dy) map is a reflection, preserving angular distances;
//  yaw 0 at segment starts corresponds to direction (0, 1)).
// Only chunks with no zero pay the sqrt/atan2 cost path.
__device__ __forceinline__ float scan_min(const float2* __restrict__ cnb,
                                          const int*    __restrict__ mb,
                                          float2 pt, float vx, float vy,
                                          int lane) {
    float lmin = INF_F;
    for (int base = 0; base < NN; base += 32) {
        const int idx = base + lane;
        float2 p = cnb[idx];
        float2 q = cnb[idx > 0 ? idx - 1 : 0];
        int    m = mb[idx];

        const bool start = (idx % n_ == 0);
        float ux = start ? 0.0f : p.x - q.x;
        float uy = start ? 1.0f : p.y - q.y;

        float dx = p.x - pt.x;
        float dy = p.y - pt.y;
        float d2 = fmaf(dx, dx, dy * dy);

        float dt = fmaf(ux, vx, uy * vy);    // dot(u, v)
        float cr = fmaf(ux, vy, -uy * vx);   // cross(u, v)

        const bool valid = (m != 1);
        const bool zero  = valid && (d2 <= 4.0f) && (dt >= 0.0f) &&
                           (cr * cr <= 3.0f * dt * dt);
        if (__ballot_sync(0xffffffffu, zero)) return 0.0f;

        // no zero in this chunk: full cost
        float cd = (d2 <= 4.0f) ? 0.0f : (fast_sqrt(d2) - 2.0f);
        float a  = atan2f(fabsf(cr), dt);    // |wrapped yaw diff|
        float c  = cd + fmaxf(a - YAW_THRESH, 0.0f);
        lmin = fminf(lmin, valid ? c : INF_F);
    }
    // warp-reduce min
    lmin = fminf(lmin, __shfl_xor_sync(0xffffffffu, lmin, 16));
    lmin = fminf(lmin, __shfl_xor_sync(0xffffffffu, lmin, 8));
    lmin = fminf(lmin, __shfl_xor_sync(0xffffffffu, lmin, 4));
    lmin = fminf(lmin, __shfl_xor_sync(0xffffffffu, lmin, 2));
    lmin = fminf(lmin, __shfl_xor_sync(0xffffffffu, lmin, 1));
    return lmin;
}

// One block per (b, k). 8 warps; warp w handles t = w, w+8, w+16, w+24.
// No smem node table: node chunks are read directly from gmem (the 30 KB/batch
// working set is L1/L2-resident and shared by all 480 warps of the batch).
__global__ __launch_bounds__(256)
void consistency_kernel(const float* __restrict__ preds,
                        const float* __restrict__ cn,
                        const int*   __restrict__ mask,
                        float* __restrict__ out) {
    const int bk = blockIdx.x;
    const int b  = bk >> 4;                 // / K_

    const float2* cnb = (const float2*)cn + (size_t)b * NN;
    const int*    mb  = mask + (size_t)b * NN;
    const float2* pp  = (const float2*)preds + (size_t)bk * T_;

    __shared__ float s_min[32];

    const int tid  = threadIdx.x;
    const int warp = tid >> 5;
    const int lane = tid & 31;

    #pragma unroll
    for (int i = 0; i < 4; ++i) {
        const int t = warp + i * 8;
        if (t >= T_) break;
        const float2 pt = pp[t];
        float vx = 0.0f, vy = 1.0f;          // yaw 0 <-> direction (0, 1)
        if (t != 0) {
            float2 pm = pp[t - 1];
            vx = pt.x - pm.x;
            vy = pt.y - pm.y;
        }
        float m = scan_min(cnb, mb, pt, vx, vy, lane);
        if (lane == 0) s_min[t] = m;
    }
    __syncthreads();

    // sum over T (deterministic shfl tree)
    if (tid < 32) {
        float v = (tid < T_) ? s_min[tid] : 0.0f;
        v += __shfl_xor_sync(0xffffffffu, v, 16);
        v += __shfl_xor_sync(0xffffffffu, v, 8);
        v += __shfl_xor_sync(0xffffffffu, v, 4);
        v += __shfl_xor_sync(0xffffffffu, v, 2);
        v += __shfl_xor_sync(0xffffffffu, v, 1);
        if (tid == 0) out[bk] = v;
    }
}

extern "C" void kernel_launch(void* const* d_in, const int* in_sizes, int n_in,
                              void* d_out, int out_size) {
    const float* preds = (const float*)d_in[0];
    const float* cn    = (const float*)d_in[1];
    const int*   mask  = (const int*)d_in[2];
    float* out = (float*)d_out;

    consistency_kernel<<<B_ * K_, 256>>>(preds, cn, mask, out);
}

// round 5
// speedup vs baseline: 1.0022x; 1.0022x over previous
#include <cuda_runtime.h>
#include <math.h>

// Problem constants (fixed by setup_inputs)
#define B_  32
#define K_  16
#define T_  30
#define N_  128
#define n_  20
#define NN  (N_ * n_)        // 2560 nodes per batch

#define YAW_THRESH  1.0471975511965976f   // pi/3
#define INF_F       __int_as_float(0x7f800000)

__device__ __forceinline__ float fast_sqrt(float x) {
    float r;
    asm("sqrt.approx.f32 %0, %1;" : "=f"(r) : "f"(x));
    return r;
}

// One block per (b, k); 1024 threads; warp t handles timestep t (t < 30).
//
// Cost(node, point) = relu(dist - 2) + relu(|wrap(yaw_n - yaw_p)| - pi/3),
// with masked nodes -> +inf. Since yaw = -atan2(dx, dy) is a reflection of
// the direction angle, |wrapped yaw diff| == angle(u, v) between raw
// direction vectors (segment starts / t=0 map to direction (0,1)).
// Exact-zero test needs no transcendentals:
//   unmasked AND d2 <= 4 AND dot(u,v) >= 0 AND cross^2 <= 3*dot^2.
// Cost >= 0 always, so the min is finalized the moment any lane sees zero.
//
// Each iteration covers 128 nodes (4 per lane): independent coalesced loads,
// cheap zero tests, ONE ballot. P(no zero in 128 random nodes) ~ 1e-8 for
// in-distribution points, so nearly every warp exits after 1 iteration; the
// sqrt/atan2 full-cost path runs only on proven zero-free iterations.
__global__ __launch_bounds__(1024)
void consistency_kernel(const float* __restrict__ preds,
                        const float* __restrict__ cn,
                        const int*   __restrict__ mask,
                        float* __restrict__ out) {
    const int bk = blockIdx.x;
    const int b  = bk >> 4;                 // / K_

    const float2* cnb = (const float2*)cn + (size_t)b * NN;
    const int*    mb  = mask + (size_t)b * NN;
    const float2* pp  = (const float2*)preds + (size_t)bk * T_;

    __shared__ float s_min[32];

    const int tid  = threadIdx.x;
    const int warp = tid >> 5;
    const int lane = tid & 31;

    if (warp < T_) {
        const int t = warp;
        const float2 pt = pp[t];
        float vx = 0.0f, vy = 1.0f;          // yaw 0 <-> direction (0, 1)
        if (t != 0) {
            float2 pm = pp[t - 1];
            vx = pt.x - pm.x;
            vy = pt.y - pm.y;
        }

        float lmin = INF_F;
        for (int base = 0; base < NN; base += 128) {
            float2 p[4], q[4];
            int    m[4];
            float  d2[4], dt[4], cr[4];
            bool   valid[4], start[4];
            bool   anyzero = false;

            #pragma unroll
            for (int j = 0; j < 4; ++j) {
                const int idx = base + j * 32 + lane;
                p[j] = cnb[idx];
                q[j] = cnb[idx > 0 ? idx - 1 : 0];
                m[j] = mb[idx];
                start[j] = ((base + j * 32 + lane) % n_ == 0);
            }

            #pragma unroll
            for (int j = 0; j < 4; ++j) {
                float ux = start[j] ? 0.0f : p[j].x - q[j].x;
                float uy = start[j] ? 1.0f : p[j].y - q[j].y;

                float dx = p[j].x - pt.x;
                float dy = p[j].y - pt.y;
                d2[j] = fmaf(dx, dx, dy * dy);
                dt[j] = fmaf(ux, vx, uy * vy);    // dot(u, v)
                cr[j] = fmaf(ux, vy, -uy * vx);   // cross(u, v)

                valid[j] = (m[j] != 1);
                bool zero = valid[j] && (d2[j] <= 4.0f) && (dt[j] >= 0.0f) &&
                            (cr[j] * cr[j] <= 3.0f * dt[j] * dt[j]);
                anyzero |= zero;
            }

            if (__ballot_sync(0xffffffffu, anyzero)) { lmin = 0.0f; break; }

            // zero-free chunk: full costs
            #pragma unroll
            for (int j = 0; j < 4; ++j) {
                float cd = (d2[j] <= 4.0f) ? 0.0f : (fast_sqrt(d2[j]) - 2.0f);
                float a  = atan2f(fabsf(cr[j]), dt[j]);  // |wrapped yaw diff|
                float c  = cd + fmaxf(a - YAW_THRESH, 0.0f);
                lmin = fminf(lmin, valid[j] ? c : INF_F);
            }
        }

        // warp-reduce min
        lmin = fminf(lmin, __shfl_xor_sync(0xffffffffu, lmin, 16));
        lmin = fminf(lmin, __shfl_xor_sync(0xffffffffu, lmin, 8));
        lmin = fminf(lmin, __shfl_xor_sync(0xffffffffu, lmin, 4));
        lmin = fminf(lmin, __shfl_xor_sync(0xffffffffu, lmin, 2));
        lmin = fminf(lmin, __shfl_xor_sync(0xffffffffu, lmin, 1));
        if (lane == 0) s_min[t] = lmin;
    } else if (lane == 0 && warp < 32) {
        s_min[warp] = 0.0f;                 // pad t = 30, 31
    }
    __syncthreads();

    // sum over T (deterministic shfl tree)
    if (tid < 32) {
        float v = s_min[tid];
        v += __shfl_xor_sync(0xffffffffu, v, 16);
        v += __shfl_xor_sync(0xffffffffu, v, 8);
        v += __shfl_xor_sync(0xffffffffu, v, 4);
        v += __shfl_xor_sync(0xffffffffu, v, 2);
        v += __shfl_xor_sync(0xffffffffu, v, 1);
        if (tid == 0) out[bk] = v;
    }
}

extern "C" void kernel_launch(void* const* d_in, const int* in_sizes, int n_in,
                              void* d_out, int out_size) {
    const float* preds = (const float*)d_in[0];
    const float* cn    = (const float*)d_in[1];
    const int*   mask  = (const int*)d_in[2];
    float* out = (float*)d_out;

    consistency_kernel<<<B_ * K_, 1024>>>(preds, cn, mask, out);
}

// round 6
// speedup vs baseline: 1.1658x; 1.1633x over previous
#include <cuda_runtime.h>
#include <math.h>

// Problem constants (fixed by setup_inputs)
#define B_  32
#define K_  16
#define T_  30
#define N_  128
#define n_  20
#define NN  (N_ * n_)        // 2560 nodes per batch
#define CHUNK0 128           // phase-A nodes per timestep

#define YAW_THRESH  1.0471975511965976f   // pi/3
#define INF_F       __int_as_float(0x7f800000)

__device__ __forceinline__ float fast_sqrt(float x) {
    float r;
    asm("sqrt.approx.f32 %0, %1;" : "=f"(r) : "f"(x));
    return r;
}

// cost = relu(dist - 2) + relu(|wrap(yaw_n - yaw_p)| - pi/3); masked -> inf.
// yaw = -atan2(dx, dy) is a reflection of the direction angle, so
// |wrapped yaw diff| == angle(u, v) between raw direction vectors
// (segment starts / t = 0 map to direction (0, 1)).
__device__ __forceinline__ float node_cost(const float2* __restrict__ cnb,
                                           const int*    __restrict__ mb,
                                           int idx, float2 pt,
                                           float vx, float vy) {
    float2 p = cnb[idx];
    float2 q = cnb[idx > 0 ? idx - 1 : 0];
    int    m = mb[idx];
    bool start = (idx % n_ == 0);
    float ux = start ? 0.0f : p.x - q.x;
    float uy = start ? 1.0f : p.y - q.y;

    float dx = p.x - pt.x;
    float dy = p.y - pt.y;
    float d2 = fmaf(dx, dx, dy * dy);
    float dt = fmaf(ux, vx, uy * vy);
    float cr = fmaf(ux, vy, -uy * vx);

    float cd = (d2 <= 4.0f) ? 0.0f : (fast_sqrt(d2) - 2.0f);
    float a  = atan2f(fabsf(cr), dt);
    float c  = cd + fmaxf(a - YAW_THRESH, 0.0f);
    return (m != 1) ? c : INF_F;
}

// One block per (b, k); 1024 threads = 32 warps; warps 0..29 <-> timesteps.
//
// Phase A: warp t tests nodes [0, 128) for exact-zero cost (no transcendentals:
//   unmasked AND d2<=4 AND dot>=0 AND cross^2 <= 3*dot^2, tan(pi/3)^2 == 3).
//   Zero found -> min is final (cost >= 0). Otherwise store the chunk's min
//   and enqueue t as unresolved.
// Phase B: for each unresolved t, ALL 1024 threads scan nodes [128, NN) in
//   parallel (<= 3 nodes/thread) and block-min-reduce. This removes the
//   serial straggler tail that dominated previous rounds.
__global__ __launch_bounds__(1024)
void consistency_kernel(const float* __restrict__ preds,
                        const float* __restrict__ cn,
                        const int*   __restrict__ mask,
                        float* __restrict__ out) {
    const int bk = blockIdx.x;
    const int b  = bk >> 4;                 // / K_

    const float2* cnb = (const float2*)cn + (size_t)b * NN;
    const int*    mb  = mask + (size_t)b * NN;
    const float2* pp  = (const float2*)preds + (size_t)bk * T_;

    __shared__ float s_min[32];
    __shared__ int   s_unres[32];
    __shared__ int   s_ucnt;
    __shared__ float s_red[32];

    const int tid  = threadIdx.x;
    const int warp = tid >> 5;
    const int lane = tid & 31;

    if (tid == 0) s_ucnt = 0;
    if (warp >= T_ && lane == 0 && warp < 32) s_min[warp] = 0.0f; // pad t=30,31
    __syncthreads();

    // ---------------- Phase A ----------------
    if (warp < T_) {
        const int t = warp;
        const float2 pt = pp[t];
        float vx = 0.0f, vy = 1.0f;          // yaw 0 <-> direction (0, 1)
        if (t != 0) {
            float2 pm = pp[t - 1];
            vx = pt.x - pm.x;
            vy = pt.y - pm.y;
        }

        float d2[4], dt[4], cr[4];
        bool  valid[4];
        bool  anyzero = false;

        #pragma unroll
        for (int j = 0; j < 4; ++j) {
            const int idx = j * 32 + lane;
            float2 p = cnb[idx];
            float2 q = cnb[idx > 0 ? idx - 1 : 0];
            int    m = mb[idx];
            bool start = (idx % n_ == 0);
            float ux = start ? 0.0f : p.x - q.x;
            float uy = start ? 1.0f : p.y - q.y;

            float dx = p.x - pt.x;
            float dy = p.y - pt.y;
            d2[j] = fmaf(dx, dx, dy * dy);
            dt[j] = fmaf(ux, vx, uy * vy);
            cr[j] = fmaf(ux, vy, -uy * vx);
            valid[j] = (m != 1);
            anyzero |= valid[j] && (d2[j] <= 4.0f) && (dt[j] >= 0.0f) &&
                       (cr[j] * cr[j] <= 3.0f * dt[j] * dt[j]);
        }

        if (__ballot_sync(0xffffffffu, anyzero)) {
            if (lane == 0) s_min[t] = 0.0f;
        } else {
            // chunk-0 full costs -> partial min
            float lmin = INF_F;
            #pragma unroll
            for (int j = 0; j < 4; ++j) {
                float cd = (d2[j] <= 4.0f) ? 0.0f : (fast_sqrt(d2[j]) - 2.0f);
                float a  = atan2f(fabsf(cr[j]), dt[j]);
                float c  = cd + fmaxf(a - YAW_THRESH, 0.0f);
                lmin = fminf(lmin, valid[j] ? c : INF_F);
            }
            lmin = fminf(lmin, __shfl_xor_sync(0xffffffffu, lmin, 16));
            lmin = fminf(lmin, __shfl_xor_sync(0xffffffffu, lmin, 8));
            lmin = fminf(lmin, __shfl_xor_sync(0xffffffffu, lmin, 4));
            lmin = fminf(lmin, __shfl_xor_sync(0xffffffffu, lmin, 2));
            lmin = fminf(lmin, __shfl_xor_sync(0xffffffffu, lmin, 1));
            if (lane == 0) {
                s_min[t] = lmin;
                int pos = atomicAdd(&s_ucnt, 1);
                s_unres[pos] = t;
            }
        }
    }
    __syncthreads();

    // ---------------- Phase B: block-cooperative straggler scans ----------
    const int ucnt = s_ucnt;
    for (int u = 0; u < ucnt; ++u) {
        const int t = s_unres[u];
        const float2 pt = pp[t];
        float vx = 0.0f, vy = 1.0f;
        if (t != 0) {
            float2 pm = pp[t - 1];
            vx = pt.x - pm.x;
            vy = pt.y - pm.y;
        }

        float lmin = INF_F;
        for (int idx = CHUNK0 + tid; idx < NN; idx += 1024)
            lmin = fminf(lmin, node_cost(cnb, mb, idx, pt, vx, vy));

        // block min-reduce
        lmin = fminf(lmin, __shfl_xor_sync(0xffffffffu, lmin, 16));
        lmin = fminf(lmin, __shfl_xor_sync(0xffffffffu, lmin, 8));
        lmin = fminf(lmin, __shfl_xor_sync(0xffffffffu, lmin, 4));
        lmin = fminf(lmin, __shfl_xor_sync(0xffffffffu, lmin, 2));
        lmin = fminf(lmin, __shfl_xor_sync(0xffffffffu, lmin, 1));
        if (lane == 0) s_red[warp] = lmin;
        __syncthreads();
        if (tid < 32) {
            float v = s_red[tid];
            v = fminf(v, __shfl_xor_sync(0xffffffffu, v, 16));
            v = fminf(v, __shfl_xor_sync(0xffffffffu, v, 8));
            v = fminf(v, __shfl_xor_sync(0xffffffffu, v, 4));
            v = fminf(v, __shfl_xor_sync(0xffffffffu, v, 2));
            v = fminf(v, __shfl_xor_sync(0xffffffffu, v, 1));
            if (tid == 0) s_min[t] = fminf(s_min[t], v);
        }
        __syncthreads();
    }

    // ---------------- Sum over T (deterministic shfl tree) ----------------
    if (tid < 32) {
        float v = s_min[tid];
        v += __shfl_xor_sync(0xffffffffu, v, 16);
        v += __shfl_xor_sync(0xffffffffu, v, 8);
        v += __shfl_xor_sync(0xffffffffu, v, 4);
        v += __shfl_xor_sync(0xffffffffu, v, 2);
        v += __shfl_xor_sync(0xffffffffu, v, 1);
        if (tid == 0) out[bk] = v;
    }
}

extern "C" void kernel_launch(void* const* d_in, const int* in_sizes, int n_in,
                              void* d_out, int out_size) {
    const float* preds = (const float*)d_in[0];
    const float* cn    = (const float*)d_in[1];
    const int*   mask  = (const int*)d_in[2];
    float* out = (float*)d_out;

    consistency_kernel<<<B_ * K_, 1024>>>(preds, cn, mask, out);
}